// round 11
// baseline (speedup 1.0000x reference)
#include <cuda_runtime.h>
#include <cuda_bf16.h>
#include <cstdint>

// Fused CrossEntropy + (LUT-remapped) BCE loss — single launch,
// coalesced smem staging, dynamic-LDS target gather.
//
// loss = ( sum_i (lse(pred_i) - pred_i[tgt_i]) + 100 * n_mismatch ) / N
// where mismatch_i = [ (argmax(pred_i) in [2,7]) != (tgt_i in [2,7]) ].
//
// R11 vs R10 (profile: DRAM 53%, issue 52%, alu 30% -> issue co-bound):
//  - v[tgt] read with ONE dynamic ld.shared.f32 from the staged tile instead
//    of a 9x(ISETP+SEL) register chain (-36 instr/thread).
//  - full blocks stage unpredicated (-5 ISETP/thread).
//  - 32-bit unit indexing (5M units < 2^31).

__device__ double g_acc = 0.0;
__device__ unsigned int g_count = 0u;

#define LOG2E 1.4426950408889634f
#define LN2   0.6931471805599453f

constexpr int THREADS = 256;
constexpr int ROWS_PER_BLOCK = 2 * THREADS;                 // 512
constexpr int UNITS_PER_BLOCK = ROWS_PER_BLOCK * 40 / 16;   // 1280 float4s

// Core of the per-row loss, minus the v[tgt] gather (done via smem).
// Returns lse + 100*[mismatch]; caller subtracts v[tgt].
__device__ __forceinline__ float row_loss_nogather(
    float v0, float v1, float v2, float v3, float v4,
    float v5, float v6, float v7, float v8, float v9, int tgt)
{
    // group maxes (FMNMX)
    const float m01 = fmaxf(v0, v1);
    const float m27 = fmaxf(fmaxf(fmaxf(v2, v3), fmaxf(v4, v5)), fmaxf(v6, v7));
    const float m89 = fmaxf(v8, v9);
    const float m = fmaxf(fmaxf(m01, m27), m89);

    // b_pred without argmax (exact under first-occurrence ties)
    const int bp = (m27 > m01) & (m27 >= m89);
    const int bt = (tgt >= 2) & (tgt <= 7);

    // sum exp2(v*log2e - m*log2e): FFMA + EX2 each
    const float mc = m * LOG2E;
    float s;
    s  = exp2f(fmaf(v0, LOG2E, -mc));
    s += exp2f(fmaf(v1, LOG2E, -mc));
    s += exp2f(fmaf(v2, LOG2E, -mc));
    s += exp2f(fmaf(v3, LOG2E, -mc));
    s += exp2f(fmaf(v4, LOG2E, -mc));
    s += exp2f(fmaf(v5, LOG2E, -mc));
    s += exp2f(fmaf(v6, LOG2E, -mc));
    s += exp2f(fmaf(v7, LOG2E, -mc));
    s += exp2f(fmaf(v8, LOG2E, -mc));
    s += exp2f(fmaf(v9, LOG2E, -mc));

    const float lse = fmaf(__log2f(s), LN2, m);

    return lse + ((bp != bt) ? 100.0f : 0.0f);
}

__global__ void __launch_bounds__(THREADS) loss_kernel(
    const float* __restrict__ pred,
    const int* __restrict__ target,
    float* __restrict__ out,
    int n_rows)
{
    __shared__ float4 s_pred[UNITS_PER_BLOCK];  // 20480 B
    __shared__ float warp_sums[8];

    const int tid = threadIdx.x;

    // ---- stage pred tile: coalesced cp.async.cg, 5 x 16B per thread ----
    const unsigned int block_unit_base =
        (unsigned int)blockIdx.x * (unsigned int)UNITS_PER_BLOCK;
    const unsigned int full_units =
        (unsigned int)(((long long)n_rows * 40) >> 4);  // whole 16B units
    const float4* __restrict__ gp = reinterpret_cast<const float4*>(pred);
    const unsigned int s_base =
        (unsigned int)__cvta_generic_to_shared(s_pred);

    if (block_unit_base + UNITS_PER_BLOCK <= full_units) {
        // full tile: unpredicated copies
#pragma unroll
        for (int k = 0; k < 5; k++) {
            const unsigned int uo = (unsigned int)(tid + k * THREADS);
            asm volatile("cp.async.cg.shared.global [%0], [%1], 16;"
                         :: "r"(s_base + uo * 16u),
                            "l"(gp + block_unit_base + uo));
        }
    } else {
#pragma unroll
        for (int k = 0; k < 5; k++) {
            const unsigned int uo = (unsigned int)(tid + k * THREADS);
            if (block_unit_base + uo < full_units) {
                asm volatile("cp.async.cg.shared.global [%0], [%1], 16;"
                             :: "r"(s_base + uo * 16u),
                                "l"(gp + block_unit_base + uo));
            }
        }
    }
    asm volatile("cp.async.commit_group;");

    // ---- targets in parallel with the staging copy ----
    const int pair = blockIdx.x * THREADS + tid;  // pair index
    const int r0 = 2 * pair;
    int t0 = 0, t1 = 0;
    const bool full_pair = (r0 + 1 < n_rows);
    const bool has_row   = (r0 < n_rows);
    if (full_pair) {
        const int2 tt = *reinterpret_cast<const int2*>(target + (size_t)2 * pair);
        t0 = tt.x; t1 = tt.y;
    } else if (has_row) {
        t0 = target[r0];
    }
    // clamp (cheap IMNMX pair) so dynamic smem reads stay in the row
    t0 = min(max(t0, 0), 9);
    t1 = min(max(t1, 0), 9);

    asm volatile("cp.async.wait_group 0;" ::: "memory");
    __syncthreads();

    // ---- compute from smem: 5 x LDS.128 at 80B stride (conflict-free) ----
    float local = 0.0f;
    if (full_pair) {
        const float4* __restrict__ sp = s_pred + tid * 5;
        const float4 q0 = sp[0];
        const float4 q1 = sp[1];
        const float4 q2 = sp[2];
        const float4 q3 = sp[3];
        const float4 q4 = sp[4];

        // v[tgt] via one dynamic LDS per row (replaces 18-instr select chain)
        const float* __restrict__ row0 = reinterpret_cast<const float*>(sp);
        const float vt0 = row0[t0];
        const float vt1 = row0[10 + t1];

        local = row_loss_nogather(q0.x, q0.y, q0.z, q0.w,
                                  q1.x, q1.y, q1.z, q1.w,
                                  q2.x, q2.y, t0) - vt0
              + row_loss_nogather(q2.z, q2.w,
                                  q3.x, q3.y, q3.z, q3.w,
                                  q4.x, q4.y, q4.z, q4.w, t1) - vt1;
    } else if (has_row) {
        // odd-N tail row: read directly from global (smem may miss last 8B)
        const float2* __restrict__ p =
            reinterpret_cast<const float2*>(pred + (size_t)r0 * 10);
        const float2 a0 = p[0];
        const float2 a1 = p[1];
        const float2 a2 = p[2];
        const float2 a3 = p[3];
        const float2 a4 = p[4];
        float v[10] = {a0.x, a0.y, a1.x, a1.y, a2.x,
                       a2.y, a3.x, a3.y, a4.x, a4.y};
        float vt = v[0];
#pragma unroll
        for (int j = 1; j < 10; j++) vt = (t0 == j) ? v[j] : vt;
        local = row_loss_nogather(v[0], v[1], v[2], v[3], v[4],
                                  v[5], v[6], v[7], v[8], v[9], t0) - vt;
    }

    // ---- block reduction: warp shuffle -> shared -> one double red ----
#pragma unroll
    for (int off = 16; off > 0; off >>= 1)
        local += __shfl_down_sync(0xFFFFFFFFu, local, off);

    const int lane = tid & 31;
    const int wid  = tid >> 5;
    if (lane == 0) warp_sums[wid] = local;
    __syncthreads();

    __shared__ bool is_last;
    if (wid == 0) {
        float blk = (lane < 8) ? warp_sums[lane] : 0.0f;
#pragma unroll
        for (int off = 4; off > 0; off >>= 1)
            blk += __shfl_down_sync(0xFFFFFFFFu, blk, off);
        if (lane == 0) {
            const double dblk = (double)blk;
            asm volatile("red.release.gpu.global.add.f64 [%0], %1;"
                         :: "l"(&g_acc), "d"(dblk) : "memory");
            unsigned int done;
            unsigned int one = 1u;
            asm volatile("atom.acq_rel.gpu.global.add.u32 %0, [%1], %2;"
                         : "=r"(done) : "l"(&g_count), "r"(one) : "memory");
            is_last = (done == gridDim.x - 1u);
        }
    }
    __syncthreads();

    // Last block finalizes: write output, reset state for next replay.
    if (is_last && tid == 0) {
        double acc;
        asm volatile("ld.acquire.gpu.global.f64 %0, [%1];"
                     : "=d"(acc) : "l"(&g_acc) : "memory");
        out[0] = (float)(acc / (double)n_rows);
        g_acc = 0.0;
        g_count = 0u;
    }
}

extern "C" void kernel_launch(void* const* d_in, const int* in_sizes, int n_in,
                              void* d_out, int out_size) {
    const float* pred   = (const float*)d_in[0];
    const int*   target = (const int*)d_in[1];
    float*       out    = (float*)d_out;

    const int n_rows  = in_sizes[1];  // target element count = N
    const int n_pairs = (n_rows + 1) / 2;
    const int blocks  = (n_pairs + THREADS - 1) / THREADS;

    loss_kernel<<<blocks, THREADS>>>(pred, target, out, n_rows);
}

// round 12
// speedup vs baseline: 1.1207x; 1.1207x over previous
#include <cuda_runtime.h>
#include <cuda_bf16.h>
#include <cstdint>

// Fused CrossEntropy + (LUT-remapped) BCE loss — persistent CTAs with
// double-buffered cp.async pipelining.
//
// loss = ( sum_i (lse(pred_i) - pred_i[tgt_i]) + 100 * n_mismatch ) / N
// where mismatch_i = [ (argmax(pred_i) in [2,7]) != (tgt_i in [2,7]) ].
//
// R12 vs R11 (profile: DRAM stuck ~52%, issue 46% after instr trim ->
// binder is the per-CTA stage->wait->compute serialization, not issue):
// persistent grid (5 CTAs/SM), two 512-row buffers per CTA, steady-state
// loop prefetches tile t+2 while computing tile t. wait_group 1 is constant
// by group accounting (2 groups up front, one per iteration after).

__device__ double g_acc = 0.0;
__device__ unsigned int g_count = 0u;

#define LOG2E 1.4426950408889634f
#define LN2   0.6931471805599453f

constexpr int THREADS = 256;
constexpr int ROWS_PER_TILE = 2 * THREADS;                 // 512
constexpr int UNITS_PER_TILE = ROWS_PER_TILE * 40 / 16;    // 1280 float4s
constexpr int MAX_RESIDENT = 148 * 5;                      // persistent grid cap

// Per-row loss minus the v[tgt] gather; caller subtracts v[tgt].
__device__ __forceinline__ float row_loss_nogather(
    float v0, float v1, float v2, float v3, float v4,
    float v5, float v6, float v7, float v8, float v9, int tgt)
{
    const float m01 = fmaxf(v0, v1);
    const float m27 = fmaxf(fmaxf(fmaxf(v2, v3), fmaxf(v4, v5)), fmaxf(v6, v7));
    const float m89 = fmaxf(v8, v9);
    const float m = fmaxf(fmaxf(m01, m27), m89);

    // b_pred without argmax (exact under first-occurrence ties)
    const int bp = (m27 > m01) & (m27 >= m89);
    const int bt = (tgt >= 2) & (tgt <= 7);

    const float mc = m * LOG2E;
    float s;
    s  = exp2f(fmaf(v0, LOG2E, -mc));
    s += exp2f(fmaf(v1, LOG2E, -mc));
    s += exp2f(fmaf(v2, LOG2E, -mc));
    s += exp2f(fmaf(v3, LOG2E, -mc));
    s += exp2f(fmaf(v4, LOG2E, -mc));
    s += exp2f(fmaf(v5, LOG2E, -mc));
    s += exp2f(fmaf(v6, LOG2E, -mc));
    s += exp2f(fmaf(v7, LOG2E, -mc));
    s += exp2f(fmaf(v8, LOG2E, -mc));
    s += exp2f(fmaf(v9, LOG2E, -mc));

    const float lse = fmaf(__log2f(s), LN2, m);

    return lse + ((bp != bt) ? 100.0f : 0.0f);
}

__global__ void __launch_bounds__(THREADS) loss_kernel(
    const float* __restrict__ pred,
    const int* __restrict__ target,
    float* __restrict__ out,
    int n_rows)
{
    __shared__ float4 s_pred[2][UNITS_PER_TILE];  // 2 x 20480 B
    __shared__ int2   s_tgt[2][THREADS];          // 2 x 2048 B
    __shared__ float  warp_sums[8];

    const int tid = threadIdx.x;
    const int G   = gridDim.x;
    const int total_tiles = (n_rows + ROWS_PER_TILE - 1) / ROWS_PER_TILE;

    const unsigned int full_units =
        (unsigned int)(((long long)n_rows * 40) >> 4);  // whole 16B units
    const float4* __restrict__ gp = reinterpret_cast<const float4*>(pred);
    const int2* __restrict__ gt = reinterpret_cast<const int2*>(target);
    const unsigned int sp_base0 =
        (unsigned int)__cvta_generic_to_shared(&s_pred[0][0]);
    const unsigned int sp_base1 =
        (unsigned int)__cvta_generic_to_shared(&s_pred[1][0]);
    const unsigned int st_base0 =
        (unsigned int)__cvta_generic_to_shared(&s_tgt[0][0]);
    const unsigned int st_base1 =
        (unsigned int)__cvta_generic_to_shared(&s_tgt[1][0]);

    // stage tile 'tile' into buffer 'buf' (this thread's 5 pred units + 1 tgt)
    auto stage = [&](int buf, int tile) {
        const unsigned int ubase =
            (unsigned int)tile * (unsigned int)UNITS_PER_TILE;
        const unsigned int spb = buf ? sp_base1 : sp_base0;
        if (ubase + UNITS_PER_TILE <= full_units) {
#pragma unroll
            for (int k = 0; k < 5; k++) {
                const unsigned int uo = (unsigned int)(tid + k * THREADS);
                asm volatile("cp.async.cg.shared.global [%0], [%1], 16;"
                             :: "r"(spb + uo * 16u), "l"(gp + ubase + uo));
            }
        } else {
#pragma unroll
            for (int k = 0; k < 5; k++) {
                const unsigned int uo = (unsigned int)(tid + k * THREADS);
                if (ubase + uo < full_units) {
                    asm volatile("cp.async.cg.shared.global [%0], [%1], 16;"
                                 :: "r"(spb + uo * 16u), "l"(gp + ubase + uo));
                }
            }
        }
        // targets: one int2 (pair) per thread, only full pairs
        const int pair = tile * THREADS + tid;
        if (2 * pair + 1 < n_rows) {
            const unsigned int stb = buf ? st_base1 : st_base0;
            asm volatile("cp.async.ca.shared.global [%0], [%1], 8;"
                         :: "r"(stb + (unsigned int)tid * 8u), "l"(gt + pair));
        }
    };

    // ---- prologue: prefetch up to 2 tiles, always commit 2 groups ----
    const int tile0 = blockIdx.x;
#pragma unroll
    for (int pf = 0; pf < 2; pf++) {
        const int t = tile0 + pf * G;
        if (t < total_tiles) stage(pf, t);
        asm volatile("cp.async.commit_group;");
    }

    // ---- steady state ----
    float local = 0.0f;
    int idx = 0;
    for (int tile = tile0; tile < total_tiles; tile += G, idx++) {
        const int buf = idx & 1;

        // groups committed = 2 + idx; need oldest idx+1 done -> wait_group 1
        asm volatile("cp.async.wait_group 1;" ::: "memory");
        __syncthreads();

        const int pair = tile * THREADS + tid;
        const int r0 = 2 * pair;
        if (r0 + 1 < n_rows) {
            const float4* __restrict__ sp = &s_pred[buf][0] + tid * 5;
            const float4 q0 = sp[0];
            const float4 q1 = sp[1];
            const float4 q2 = sp[2];
            const float4 q3 = sp[3];
            const float4 q4 = sp[4];
            const int2 tt = s_tgt[buf][tid];
            const int t0 = min(max(tt.x, 0), 9);
            const int t1 = min(max(tt.y, 0), 9);

            const float* __restrict__ row0 =
                reinterpret_cast<const float*>(sp);
            const float vt0 = row0[t0];
            const float vt1 = row0[10 + t1];

            local += row_loss_nogather(q0.x, q0.y, q0.z, q0.w,
                                       q1.x, q1.y, q1.z, q1.w,
                                       q2.x, q2.y, t0) - vt0
                   + row_loss_nogather(q2.z, q2.w,
                                       q3.x, q3.y, q3.z, q3.w,
                                       q4.x, q4.y, q4.z, q4.w, t1) - vt1;
        } else if (r0 < n_rows) {
            // odd-N single tail row: read directly from global
            const float2* __restrict__ p =
                reinterpret_cast<const float2*>(pred + (size_t)r0 * 10);
            const float2 a0 = p[0];
            const float2 a1 = p[1];
            const float2 a2 = p[2];
            const float2 a3 = p[3];
            const float2 a4 = p[4];
            float v[10] = {a0.x, a0.y, a1.x, a1.y, a2.x,
                           a2.y, a3.x, a3.y, a4.x, a4.y};
            int t0 = min(max(target[r0], 0), 9);
            float vt = v[0];
#pragma unroll
            for (int j = 1; j < 10; j++) vt = (t0 == j) ? v[j] : vt;
            local += row_loss_nogather(v[0], v[1], v[2], v[3], v[4],
                                       v[5], v[6], v[7], v[8], v[9], t0) - vt;
        }

        __syncthreads();  // everyone done reading buf before overwrite

        const int pft = tile + 2 * G;
        if (pft < total_tiles) stage(buf, pft);
        asm volatile("cp.async.commit_group;");
    }
    // drain any remaining (empty/unconsumed) groups
    asm volatile("cp.async.wait_group 0;" ::: "memory");

    // ---- block reduction: warp shuffle -> shared -> one double red ----
#pragma unroll
    for (int off = 16; off > 0; off >>= 1)
        local += __shfl_down_sync(0xFFFFFFFFu, local, off);

    const int lane = tid & 31;
    const int wid  = tid >> 5;
    if (lane == 0) warp_sums[wid] = local;
    __syncthreads();

    __shared__ bool is_last;
    if (wid == 0) {
        float blk = (lane < 8) ? warp_sums[lane] : 0.0f;
#pragma unroll
        for (int off = 4; off > 0; off >>= 1)
            blk += __shfl_down_sync(0xFFFFFFFFu, blk, off);
        if (lane == 0) {
            const double dblk = (double)blk;
            asm volatile("red.release.gpu.global.add.f64 [%0], %1;"
                         :: "l"(&g_acc), "d"(dblk) : "memory");
            unsigned int done;
            unsigned int one = 1u;
            asm volatile("atom.acq_rel.gpu.global.add.u32 %0, [%1], %2;"
                         : "=r"(done) : "l"(&g_count), "r"(one) : "memory");
            is_last = (done == gridDim.x - 1u);
        }
    }
    __syncthreads();

    // Last block finalizes: write output, reset state for next replay.
    if (is_last && tid == 0) {
        double acc;
        asm volatile("ld.acquire.gpu.global.f64 %0, [%1];"
                     : "=d"(acc) : "l"(&g_acc) : "memory");
        out[0] = (float)(acc / (double)n_rows);
        g_acc = 0.0;
        g_count = 0u;
    }
}

extern "C" void kernel_launch(void* const* d_in, const int* in_sizes, int n_in,
                              void* d_out, int out_size) {
    const float* pred   = (const float*)d_in[0];
    const int*   target = (const int*)d_in[1];
    float*       out    = (float*)d_out;

    const int n_rows = in_sizes[1];  // target element count = N
    const int total_tiles = (n_rows + ROWS_PER_TILE - 1) / ROWS_PER_TILE;
    const int blocks = (total_tiles < MAX_RESIDENT) ? total_tiles : MAX_RESIDENT;

    loss_kernel<<<blocks, THREADS>>>(pred, target, out, n_rows);
}

// round 13
// speedup vs baseline: 1.1426x; 1.0195x over previous
#include <cuda_runtime.h>
#include <cuda_bf16.h>
#include <cstdint>

// Fused CrossEntropy + (LUT-remapped) BCE loss — persistent CTAs,
// WARP-LOCAL double-buffered cp.async pipelines (no block barriers in loop).
//
// loss = ( sum_i (lse(pred_i) - pred_i[tgt_i]) + 100 * n_mismatch ) / N
// where mismatch_i = [ (argmax(pred_i) in [2,7]) != (tgt_i in [2,7]) ].
//
// R13 vs R12: each warp stages exactly the 160 float4 units its own lanes
// consume (uo = w*160 + lane + k*32; still 512B contiguous per instruction,
// same coalescing). Cross-warp deps gone -> __syncthreads in the hot loop
// becomes __syncwarp. 8 independent pipelines per CTA; a warp stalled on
// wait_group no longer convoys the other 7 at a BAR.

__device__ double g_acc = 0.0;
__device__ unsigned int g_count = 0u;

#define LOG2E 1.4426950408889634f
#define LN2   0.6931471805599453f

constexpr int THREADS = 256;
constexpr int ROWS_PER_TILE = 2 * THREADS;                 // 512
constexpr int UNITS_PER_TILE = ROWS_PER_TILE * 40 / 16;    // 1280 float4s
constexpr int UNITS_PER_WARP = UNITS_PER_TILE / 8;         // 160
constexpr int MAX_RESIDENT = 148 * 5;                      // persistent grid cap

// Per-row loss minus the v[tgt] gather; caller subtracts v[tgt].
__device__ __forceinline__ float row_loss_nogather(
    float v0, float v1, float v2, float v3, float v4,
    float v5, float v6, float v7, float v8, float v9, int tgt)
{
    const float m01 = fmaxf(v0, v1);
    const float m27 = fmaxf(fmaxf(fmaxf(v2, v3), fmaxf(v4, v5)), fmaxf(v6, v7));
    const float m89 = fmaxf(v8, v9);
    const float m = fmaxf(fmaxf(m01, m27), m89);

    // b_pred without argmax (exact under first-occurrence ties)
    const int bp = (m27 > m01) & (m27 >= m89);
    const int bt = (tgt >= 2) & (tgt <= 7);

    const float mc = m * LOG2E;
    float s;
    s  = exp2f(fmaf(v0, LOG2E, -mc));
    s += exp2f(fmaf(v1, LOG2E, -mc));
    s += exp2f(fmaf(v2, LOG2E, -mc));
    s += exp2f(fmaf(v3, LOG2E, -mc));
    s += exp2f(fmaf(v4, LOG2E, -mc));
    s += exp2f(fmaf(v5, LOG2E, -mc));
    s += exp2f(fmaf(v6, LOG2E, -mc));
    s += exp2f(fmaf(v7, LOG2E, -mc));
    s += exp2f(fmaf(v8, LOG2E, -mc));
    s += exp2f(fmaf(v9, LOG2E, -mc));

    const float lse = fmaf(__log2f(s), LN2, m);

    return lse + ((bp != bt) ? 100.0f : 0.0f);
}

__global__ void __launch_bounds__(THREADS) loss_kernel(
    const float* __restrict__ pred,
    const int* __restrict__ target,
    float* __restrict__ out,
    int n_rows)
{
    __shared__ float4 s_pred[2][UNITS_PER_TILE];  // 2 x 20480 B
    __shared__ int2   s_tgt[2][THREADS];          // 2 x 2048 B
    __shared__ float  warp_sums[8];

    const int tid  = threadIdx.x;
    const int lane = tid & 31;
    const int w    = tid >> 5;
    const int G    = gridDim.x;
    const int total_tiles = (n_rows + ROWS_PER_TILE - 1) / ROWS_PER_TILE;

    const unsigned int full_units =
        (unsigned int)(((long long)n_rows * 40) >> 4);  // whole 16B units
    const float4* __restrict__ gp = reinterpret_cast<const float4*>(pred);
    const int2* __restrict__ gt = reinterpret_cast<const int2*>(target);
    const unsigned int sp_base0 =
        (unsigned int)__cvta_generic_to_shared(&s_pred[0][0]);
    const unsigned int sp_base1 =
        (unsigned int)__cvta_generic_to_shared(&s_pred[1][0]);
    const unsigned int st_base0 =
        (unsigned int)__cvta_generic_to_shared(&s_tgt[0][0]);
    const unsigned int st_base1 =
        (unsigned int)__cvta_generic_to_shared(&s_tgt[1][0]);

    const unsigned int warp_unit0 = (unsigned int)(w * UNITS_PER_WARP);

    // Stage this WARP's slice of tile 'tile' into buffer 'buf'.
    // Units staged == units this warp's lanes consume. 512B/instr coalesced.
    auto stage = [&](int buf, int tile) {
        const unsigned int ubase =
            (unsigned int)tile * (unsigned int)UNITS_PER_TILE + warp_unit0;
        const unsigned int spb =
            (buf ? sp_base1 : sp_base0) + warp_unit0 * 16u;
        if (ubase + UNITS_PER_WARP <= full_units) {
#pragma unroll
            for (int k = 0; k < 5; k++) {
                const unsigned int uo = (unsigned int)(lane + k * 32);
                asm volatile("cp.async.cg.shared.global [%0], [%1], 16;"
                             :: "r"(spb + uo * 16u), "l"(gp + ubase + uo));
            }
        } else {
#pragma unroll
            for (int k = 0; k < 5; k++) {
                const unsigned int uo = (unsigned int)(lane + k * 32);
                if (ubase + uo < full_units) {
                    asm volatile("cp.async.cg.shared.global [%0], [%1], 16;"
                                 :: "r"(spb + uo * 16u), "l"(gp + ubase + uo));
                }
            }
        }
        // target pair: thread-local (stages what it consumes)
        const int pair = tile * THREADS + tid;
        if (2 * pair + 1 < n_rows) {
            const unsigned int stb = buf ? st_base1 : st_base0;
            asm volatile("cp.async.ca.shared.global [%0], [%1], 8;"
                         :: "r"(stb + (unsigned int)tid * 8u), "l"(gt + pair));
        }
    };

    // ---- prologue: prefetch up to 2 tiles, always commit 2 groups ----
    const int tile0 = blockIdx.x;
#pragma unroll
    for (int pf = 0; pf < 2; pf++) {
        const int t = tile0 + pf * G;
        if (t < total_tiles) stage(pf, t);
        asm volatile("cp.async.commit_group;");
    }

    // ---- steady state: warp-local pipeline, no block barriers ----
    float local = 0.0f;
    int idx = 0;
    for (int tile = tile0; tile < total_tiles; tile += G, idx++) {
        const int buf = idx & 1;

        // groups committed = 2 + idx; need oldest idx+1 done -> wait_group 1
        asm volatile("cp.async.wait_group 1;" ::: "memory");
        __syncwarp();  // all lanes' copies for this warp's slice are done

        const int pair = tile * THREADS + tid;
        const int r0 = 2 * pair;
        if (r0 + 1 < n_rows) {
            const float4* __restrict__ sp = &s_pred[buf][0] + tid * 5;
            const float4 q0 = sp[0];
            const float4 q1 = sp[1];
            const float4 q2 = sp[2];
            const float4 q3 = sp[3];
            const float4 q4 = sp[4];
            const int2 tt = s_tgt[buf][tid];
            const int t0 = min(max(tt.x, 0), 9);
            const int t1 = min(max(tt.y, 0), 9);

            const float* __restrict__ row0 =
                reinterpret_cast<const float*>(sp);
            const float vt0 = row0[t0];
            const float vt1 = row0[10 + t1];

            local += row_loss_nogather(q0.x, q0.y, q0.z, q0.w,
                                       q1.x, q1.y, q1.z, q1.w,
                                       q2.x, q2.y, t0) - vt0
                   + row_loss_nogather(q2.z, q2.w,
                                       q3.x, q3.y, q3.z, q3.w,
                                       q4.x, q4.y, q4.z, q4.w, t1) - vt1;
        } else if (r0 < n_rows) {
            // odd-N single tail row: read directly from global
            const float2* __restrict__ p =
                reinterpret_cast<const float2*>(pred + (size_t)r0 * 10);
            const float2 a0 = p[0];
            const float2 a1 = p[1];
            const float2 a2 = p[2];
            const float2 a3 = p[3];
            const float2 a4 = p[4];
            float v[10] = {a0.x, a0.y, a1.x, a1.y, a2.x,
                           a2.y, a3.x, a3.y, a4.x, a4.y};
            int t0 = min(max(target[r0], 0), 9);
            float vt = v[0];
#pragma unroll
            for (int j = 1; j < 10; j++) vt = (t0 == j) ? v[j] : vt;
            local += row_loss_nogather(v[0], v[1], v[2], v[3], v[4],
                                       v[5], v[6], v[7], v[8], v[9], t0) - vt;
        }

        __syncwarp();  // warp done reading its slice before re-staging it

        const int pft = tile + 2 * G;
        if (pft < total_tiles) stage(buf, pft);
        asm volatile("cp.async.commit_group;");
    }
    // drain remaining groups
    asm volatile("cp.async.wait_group 0;" ::: "memory");

    // ---- block reduction: warp shuffle -> shared -> one double red ----
#pragma unroll
    for (int off = 16; off > 0; off >>= 1)
        local += __shfl_down_sync(0xFFFFFFFFu, local, off);

    if (lane == 0) warp_sums[w] = local;
    __syncthreads();

    __shared__ bool is_last;
    if (w == 0) {
        float blk = (lane < 8) ? warp_sums[lane] : 0.0f;
#pragma unroll
        for (int off = 4; off > 0; off >>= 1)
            blk += __shfl_down_sync(0xFFFFFFFFu, blk, off);
        if (lane == 0) {
            const double dblk = (double)blk;
            asm volatile("red.release.gpu.global.add.f64 [%0], %1;"
                         :: "l"(&g_acc), "d"(dblk) : "memory");
            unsigned int done;
            unsigned int one = 1u;
            asm volatile("atom.acq_rel.gpu.global.add.u32 %0, [%1], %2;"
                         : "=r"(done) : "l"(&g_count), "r"(one) : "memory");
            is_last = (done == gridDim.x - 1u);
        }
    }
    __syncthreads();

    // Last block finalizes: write output, reset state for next replay.
    if (is_last && tid == 0) {
        double acc;
        asm volatile("ld.acquire.gpu.global.f64 %0, [%1];"
                     : "=d"(acc) : "l"(&g_acc) : "memory");
        out[0] = (float)(acc / (double)n_rows);
        g_acc = 0.0;
        g_count = 0u;
    }
}

extern "C" void kernel_launch(void* const* d_in, const int* in_sizes, int n_in,
                              void* d_out, int out_size) {
    const float* pred   = (const float*)d_in[0];
    const int*   target = (const int*)d_in[1];
    float*       out    = (float*)d_out;

    const int n_rows = in_sizes[1];  // target element count = N
    const int total_tiles = (n_rows + ROWS_PER_TILE - 1) / ROWS_PER_TILE;
    const int blocks = (total_tiles < MAX_RESIDENT) ? total_tiles : MAX_RESIDENT;

    loss_kernel<<<blocks, THREADS>>>(pred, target, out, n_rows);
}